// round 13
// baseline (speedup 1.0000x reference)
#include <cuda_runtime.h>
#include <cstdint>
#include <cstddef>

#define TT   512
#define BB   128
#define EE   512
#define HH   512
#define G5   2560
#define LEE  512
#define EPSV 1e-5f
#define NBLK 128      // LSTM persistent blocks (1 per SM, co-resident)
#define UB   8        // units per LSTM block
#define SBL  64       // slots per LSTM block
#define CKL  128      // LSTM k-chunk

// ------------------------- static device scratch ---------------------------
__device__ float    g_pre[(size_t)TT * BB * G5];   // [t*128+b][2560]
__device__ float    g_hbuf[3][BB * HH];            // rotating hidden (SLOT space)
__device__ float    g_xsel[BB * HH];               // outs[label_len[b], b] (real b)
__device__ float    g_z0[BB * LEE];
__device__ unsigned g_sync;
__device__ int      g_slot2b[BB];                  // slot (=rank) -> real batch
__device__ int      g_Lslot[BB];                   // slot -> label_len (ascending)
__device__ int      g_maxL;

// ------------------- packed f32x2 FMA (sm_103a FFMA2) ----------------------
union F2U { float2 f; unsigned long long u; };
struct F4v { F2U lo, hi; };   // 16B = two f32x2 lanes
__device__ __forceinline__ void ffma2(F2U& acc, F2U a, F2U b) {
    asm("fma.rn.f32x2 %0, %1, %2, %0;" : "+l"(acc.u) : "l"(a.u), "l"(b.u));
}
__device__ __forceinline__ float sgm(float x) { return 1.f / (1.f + __expf(-x)); }
__device__ __forceinline__ float tanh_fast(float x) {
    return 1.f - 2.f / (1.f + __expf(2.f * x));
}

// ------------------ profiling-alignment no-op launch -----------------------
__global__ void k_nop() {}

// --------------------------- init + length sort ----------------------------
__global__ void k_init(const int* __restrict__ llen) {
    int i = blockIdx.x * blockDim.x + threadIdx.x;
    if (i < BB * HH) g_hbuf[0][i] = 0.f;
    if (blockIdx.x == 0) {
        if (threadIdx.x == 0) g_sync = 0u;
        if (threadIdx.x < BB) {
            int b  = threadIdx.x;
            int Lb = llen[b];
            int r = 0, mx = 0;
            #pragma unroll 4
            for (int j = 0; j < BB; j++) {
                int Lj = llen[j];
                r  += (Lj < Lb) || (Lj == Lb && j < b);
                mx  = max(mx, Lj);
            }
            g_slot2b[r] = b;      // slot == stable rank (ascending L)
            g_Lslot[r]  = Lb;
            if (threadIdx.x == 0) g_maxL = mx;
        }
    }
}

// ---------------- K1: pre = gather(embed) @ i2h_w^T + i2h_b ----------------
// (unchanged — profiled at 69.4% fma pipe)
__global__ __launch_bounds__(256, 2)
void k_pre(const int* __restrict__ label, const float* __restrict__ embed_w,
           const float* __restrict__ i2h_w, const float* __restrict__ i2h_b)
{
    __shared__ __align__(16) float As[2][16][128];
    __shared__ __align__(16) float Ws[2][16][128];

    const int tid = threadIdx.x;
    const int tx = tid & 15, ty = tid >> 4;
    const int n0 = blockIdx.x * 128, m0 = blockIdx.y * 128;
    const int ml = tid >> 1, lk = (tid & 1) * 8;

    const int m = m0 + ml, t_ = m >> 7, b_ = m & 127;
    const float* arow = embed_w + (size_t)label[b_ * TT + t_] * EE;
    const float* wrow = i2h_w + (size_t)(n0 + ml) * EE;

    F2U acc[8][4];
    #pragma unroll
    for (int i = 0; i < 8; i++)
        #pragma unroll
        for (int j = 0; j < 4; j++) acc[i][j].u = 0ull;

    float4 ra0 = *(const float4*)(arow + lk);
    float4 ra1 = *(const float4*)(arow + lk + 4);
    float4 rw0 = *(const float4*)(wrow + lk);
    float4 rw1 = *(const float4*)(wrow + lk + 4);

    #pragma unroll 1
    for (int ko = 0; ko < EE / 16; ++ko) {
        const int buf = ko & 1;
        As[buf][lk + 0][ml] = ra0.x; As[buf][lk + 1][ml] = ra0.y;
        As[buf][lk + 2][ml] = ra0.z; As[buf][lk + 3][ml] = ra0.w;
        As[buf][lk + 4][ml] = ra1.x; As[buf][lk + 5][ml] = ra1.y;
        As[buf][lk + 6][ml] = ra1.z; As[buf][lk + 7][ml] = ra1.w;
        Ws[buf][lk + 0][ml] = rw0.x; Ws[buf][lk + 1][ml] = rw0.y;
        Ws[buf][lk + 2][ml] = rw0.z; Ws[buf][lk + 3][ml] = rw0.w;
        Ws[buf][lk + 4][ml] = rw1.x; Ws[buf][lk + 5][ml] = rw1.y;
        Ws[buf][lk + 6][ml] = rw1.z; Ws[buf][lk + 7][ml] = rw1.w;
        __syncthreads();
        if (ko + 1 < EE / 16) {
            const int kb = (ko + 1) * 16 + lk;
            ra0 = *(const float4*)(arow + kb);
            ra1 = *(const float4*)(arow + kb + 4);
            rw0 = *(const float4*)(wrow + kb);
            rw1 = *(const float4*)(wrow + kb + 4);
        }
        #pragma unroll
        for (int k = 0; k < 16; ++k) {
            float4 aA = *(const float4*)&As[buf][k][ty * 8];       // broadcast
            float4 aB = *(const float4*)&As[buf][k][ty * 8 + 4];   // broadcast
            F4v bA = *(const F4v*)&Ws[buf][k][tx * 4];             // conflict-free
            F4v bB = *(const F4v*)&Ws[buf][k][64 + tx * 4];        // conflict-free
            float av[8] = {aA.x, aA.y, aA.z, aA.w, aB.x, aB.y, aB.z, aB.w};
            #pragma unroll
            for (int i = 0; i < 8; i++) {
                F2U ad; ad.f.x = av[i]; ad.f.y = av[i];
                ffma2(acc[i][0], ad, bA.lo);
                ffma2(acc[i][1], ad, bA.hi);
                ffma2(acc[i][2], ad, bB.lo);
                ffma2(acc[i][3], ad, bB.hi);
            }
        }
    }

    const float4 bi0 = *(const float4*)(i2h_b + n0 + tx * 4);
    const float4 bi1 = *(const float4*)(i2h_b + n0 + 64 + tx * 4);
    #pragma unroll
    for (int i = 0; i < 8; i++) {
        const int mrow = m0 + ty * 8 + i;
        float* op = g_pre + (size_t)mrow * G5 + n0 + tx * 4;
        float4 o0, o1;
        o0.x = acc[i][0].f.x + bi0.x; o0.y = acc[i][0].f.y + bi0.y;
        o0.z = acc[i][1].f.x + bi0.z; o0.w = acc[i][1].f.y + bi0.w;
        o1.x = acc[i][2].f.x + bi1.x; o1.y = acc[i][2].f.y + bi1.y;
        o1.z = acc[i][3].f.x + bi1.z; o1.w = acc[i][3].f.y + bi1.w;
        *(float4*)op        = o0;
        *(float4*)(op + 64) = o1;
    }
}

// ------------------------- K2: persistent LSTM -----------------------------
// 128 blocks = 64 unit-groups (8 units) x 2 slot-groups (64 slots).
// 512 threads: thread (u = tid>>6, s = tid&63) computes unit ju = ug*8+u for
// global slot sg*64+s (slot == length-sorted rank). Warps span 32 consecutive
// ranks -> coherent early exit via __any_sync. Cell state in registers.
// Pre-activations staged cooperatively (coalesced, double-buffered, one step
// ahead); h outputs staged through SMEM for coalesced global writes.
__global__ __launch_bounds__(512, 1)
void k_lstm(const float* __restrict__ h2h_w, const float* __restrict__ h2h_b)
{
    extern __shared__ float sm[];
    float* w_s    = sm;                            // [40][512]      = 20480 f
    float* h_s    = sm + 20480;                    // [2][32][64][4] = 16384 f
    float* sm_pre = sm + 20480 + 16384;            // [2][40][65]    =  5200 f
    float* sm_h   = sm + 20480 + 16384 + 5200;     // [64][9]        =   576 f

    const int tid = threadIdx.x;
    const int u   = tid >> 6;              // 0..7 unit within block
    const int s   = tid & 63;              // local slot (warp = 32 consec ranks)
    const int blk = blockIdx.x;
    const int ug  = blk >> 1;              // 0..63
    const int sg  = blk & 1;               // 0..1
    const int ju  = ug * UB + u;           // global unit
    const int gs  = sg * SBL + s;          // global slot (= rank)

    // resident weights: 40 rows (g*8+u) x 512 = 80 KB
    for (int i = tid; i < 5120; i += 512) {
        int r = i >> 7, k4 = i & 127;
        int g = r >> 3, uu = r & 7;
        *(float4*)(w_s + r * 512 + k4 * 4) =
            *(const float4*)(h2h_w + (size_t)(g * HH + ug * UB + uu) * HH + k4 * 4);
    }

    float bias[5];
    #pragma unroll
    for (int g = 0; g < 5; g++) bias[g] = h2h_b[g * HH + ju];

    const int bA   = g_slot2b[gs];
    const int L    = g_Lslot[gs];
    const int maxT = g_maxL;

    // h stager mapping: thread loads 64 consecutive bytes of row ls
    const int ls = tid & 63, lh = tid >> 6;          // row, k-segment
    const int Lrow = g_Lslot[sg * SBL + ls];

    // pre loader mapping: (s2, u2) -> 8 consecutive units per 4 slots (coalesced)
    const int s2 = tid >> 3, u2 = tid & 7;
    const int b2  = g_slot2b[sg * SBL + s2];
    const int L2v = g_Lslot[sg * SBL + s2];

    // h writer mapping (tid < 128): row rw_, unit-half hf
    const int rw_ = tid >> 1, hf = tid & 1;
    const int Lw = (tid < 128) ? g_Lslot[sg * SBL + rw_] : -1;

    // initial pre load for t = 0 into buffer 0
    #pragma unroll
    for (int g = 0; g < 5; g++)
        sm_pre[(g * 8 + u2) * 65 + s2] =
            __ldg(g_pre + (size_t)b2 * G5 + g * HH + ug * UB + u2);

    float cC = 0.f;
    __syncthreads();

    #pragma unroll 1
    for (int t = 0; t <= maxT; ++t) {
        const float* hcur = g_hbuf[t % 3];
        float*       hnxt = g_hbuf[(t + 1) % 3];
        const int  pbuf = (t & 1) * 2600;
        const int  nbuf = 2600 - pbuf;
        const bool act  = (t <= L);
        const bool anyAct = __any_sync(0xffffffffu, act);
        const bool stg  = (t <= Lrow);

        F2U acc[5];
        #pragma unroll
        for (int g = 0; g < 5; g++) acc[g].u = 0ull;

        float pv[5] = {0.f, 0.f, 0.f, 0.f, 0.f};
        if (act) {
            #pragma unroll
            for (int g = 0; g < 5; g++)
                pv[g] = sm_pre[pbuf + (g * 8 + u) * 65 + s];
        }

        // prefetch chunk 0 of staged row (L2 path: peers' h writes)
        float4 rg[4];
        if (stg) {
            const float* src = hcur + (size_t)(sg * SBL + ls) * HH + lh * 16;
            #pragma unroll
            for (int q = 0; q < 4; q++) rg[q] = __ldcg((const float4*)(src + q * 4));
        }

        #pragma unroll 1
        for (int ch = 0; ch < 4; ++ch) {            // 4 chunks of 128 k
            float* hb = h_s + (ch & 1) * 8192;
            if (stg) {
                #pragma unroll
                for (int q = 0; q < 4; q++)         // h_s[k4 = lh*4+q][ls][0..3]
                    *(float4*)(hb + ((lh * 4 + q) * SBL + ls) * 4) = rg[q];
            }
            __syncthreads();                        // single sync (double buffer)
            if (stg && ch < 3) {
                const float* src = hcur + (size_t)(sg * SBL + ls) * HH
                                   + (ch + 1) * CKL + lh * 16;
                #pragma unroll
                for (int q = 0; q < 4; q++) rg[q] = __ldcg((const float4*)(src + q * 4));
            }
            if (ch == 0 && (t + 1 <= L2v)) {        // next-step pre (coalesced)
                #pragma unroll
                for (int g = 0; g < 5; g++)
                    sm_pre[nbuf + (g * 8 + u2) * 65 + s2] =
                        __ldg(g_pre + ((size_t)(t + 1) * BB + b2) * G5
                              + g * HH + ug * UB + u2);
            }
            if (anyAct) {
                const F4v* hp = (const F4v*)hb;
                #pragma unroll 4
                for (int kq = 0; kq < 32; ++kq) {
                    F4v hv = hp[kq * SBL + s];       // conflict-free LDS.128
                    #pragma unroll
                    for (int g = 0; g < 5; g++) {
                        F4v wv = *(const F4v*)(w_s + (g * 8 + u) * 512
                                               + ch * CKL + kq * 4);  // broadcast
                        ffma2(acc[g], hv.lo, wv.lo);
                        ffma2(acc[g], hv.hi, wv.hi);
                    }
                }
            }
        }

        if (act) {
            float sv[5];
            #pragma unroll
            for (int g = 0; g < 5; g++)
                sv[g] = acc[g].f.x + acc[g].f.y + bias[g] + pv[g];
            float ig = sgm(sv[0]), fg = sgm(sv[1]), og = sgm(sv[2]);
            float av = fmaxf(sv[3], sv[4]);
            cC = fg * cC + ig * av;
            float nh = og * tanh_fast(cC);
            sm_h[s * 9 + u] = nh;                   // conflict-free (9 coprime 32)
            if (t == L) g_xsel[(size_t)bA * HH + ju] = nh;
        }
        __syncthreads();
        if (tid < 128 && t <= Lw) {                 // coalesced h write (full sectors)
            float4 o;
            o.x = sm_h[rw_ * 9 + hf * 4 + 0];
            o.y = sm_h[rw_ * 9 + hf * 4 + 1];
            o.z = sm_h[rw_ * 9 + hf * 4 + 2];
            o.w = sm_h[rw_ * 9 + hf * 4 + 3];
            *(float4*)(hnxt + (size_t)(sg * SBL + rw_) * HH + ug * UB + hf * 4) = o;
        }
        __syncthreads();
        if (tid == 0) {                             // grid barrier
            asm volatile("red.release.gpu.global.add.u32 [%0], 1;"
                         :: "l"(&g_sync) : "memory");
            const unsigned tgt = (unsigned)(t + 1) * NBLK;
            unsigned v;
            do {
                asm volatile("ld.acquire.gpu.u32 %0, [%1];"
                             : "=r"(v) : "l"(&g_sync));
            } while (v < tgt);
        }
        __syncthreads();
    }
}

// ---------------- K3: linear + batchnorm (+relu), one block per column -----
__global__ __launch_bounds__(128, 8)
void k_head(const float* __restrict__ w, const float* __restrict__ bias,
            const float* __restrict__ gam, const float* __restrict__ bet,
            float* __restrict__ dout, int phase)
{
    __shared__ float w_s[LEE];
    __shared__ float red[BB];
    const int n = blockIdx.x, b = threadIdx.x;
    const float* x   = phase ? g_z0 : g_xsel;
    float*       out = phase ? dout : g_z0;

    for (int k = b; k < LEE; k += BB) w_s[k] = w[(size_t)n * LEE + k];
    __syncthreads();

    float s = 0.f;
    const float* xr = x + (size_t)b * LEE;
    #pragma unroll 4
    for (int k = 0; k < LEE; k += 4) {
        float4 xv = *(const float4*)(xr + k);
        float4 wv = *(const float4*)(w_s + k);
        s += xv.x * wv.x + xv.y * wv.y + xv.z * wv.z + xv.w * wv.w;
    }
    s += bias[n];

    red[b] = s; __syncthreads();
    #pragma unroll
    for (int off = 64; off > 0; off >>= 1) {
        if (b < off) red[b] += red[b + off];
        __syncthreads();
    }
    const float mean = red[0] * (1.f / BB);
    __syncthreads();
    const float d = s - mean;
    red[b] = d * d; __syncthreads();
    #pragma unroll
    for (int off = 64; off > 0; off >>= 1) {
        if (b < off) red[b] += red[b + off];
        __syncthreads();
    }
    const float var = red[0] * (1.f / BB);

    float y = d * rsqrtf(var + EPSV) * gam[n] + bet[n];
    if (!phase) y = fmaxf(y, 0.f);
    out[(size_t)b * LEE + n] = y;
}

// ------------------------------ launcher -----------------------------------
extern "C" void kernel_launch(void* const* d_in, const int* in_sizes, int n_in,
                              void* d_out, int out_size)
{
    const int*   label    = (const int*)  d_in[0];
    const int*   llen     = (const int*)  d_in[1];
    const float* embed_w  = (const float*)d_in[2];
    const float* i2h_w    = (const float*)d_in[3];
    const float* i2h_b    = (const float*)d_in[4];
    const float* h2h_w    = (const float*)d_in[5];
    const float* h2h_b    = (const float*)d_in[6];
    const float* lin0_w   = (const float*)d_in[7];
    const float* lin0_b   = (const float*)d_in[8];
    const float* bn0_g    = (const float*)d_in[9];
    const float* bn0_b    = (const float*)d_in[10];
    const float* lin1_w   = (const float*)d_in[11];
    const float* lin1_b   = (const float*)d_in[12];
    const float* bn1_g    = (const float*)d_in[13];
    const float* bn1_b    = (const float*)d_in[14];
    float*       out      = (float*)d_out;

    const int smem_lstm = (20480 + 16384 + 5200 + 576) * (int)sizeof(float); // ~167KB
    static int attr_done = 0;
    if (!attr_done) {
        cudaFuncSetAttribute(k_lstm, cudaFuncAttributeMaxDynamicSharedMemorySize,
                             smem_lstm);
        attr_done = 1;
    }

    // launch order keeps k_lstm at position 4 (the slot ncu captures)
    k_init<<<256, 256>>>(llen);
    k_pre<<<dim3(G5 / 128, (TT * BB) / 128), 256>>>(label, embed_w, i2h_w, i2h_b);
    k_nop<<<1, 32>>>();
    k_lstm<<<NBLK, 512, smem_lstm>>>(h2h_w, h2h_b);
    k_head<<<LEE, BB>>>(lin0_w, lin0_b, bn0_g, bn0_b, out, 0);
    k_head<<<LEE, BB>>>(lin1_w, lin1_b, bn1_g, bn1_b, out, 1);
}

// round 17
// speedup vs baseline: 1.1451x; 1.1451x over previous
#include <cuda_runtime.h>
#include <cstdint>
#include <cstddef>

#define TT   512
#define BB   128
#define EE   512
#define HH   512
#define G5   2560
#define LEE  512
#define EPSV 1e-5f
#define NBLK 128      // LSTM persistent blocks (1 per SM, co-resident)
#define UB   8        // units per LSTM block
#define SBL  64       // slots per LSTM block
#define CKL  128      // LSTM k-chunk

// ------------------------- static device scratch ---------------------------
__device__ float    g_pre[(size_t)TT * BB * G5];   // [t*128+b][2560]
__device__ float    g_hbuf[3][BB * HH];            // rotating hidden (SLOT space)
__device__ float    g_xsel[BB * HH];               // outs[label_len[b], b] (real b)
__device__ float    g_z0[BB * LEE];
__device__ unsigned g_sync;
__device__ int      g_slot2b[BB];                  // slot (=rank) -> real batch
__device__ int      g_Lslot[BB];                   // slot -> label_len (ascending)
__device__ int      g_maxL;

// ------------------- packed f32x2 FMA (sm_103a FFMA2) ----------------------
union F2U { float2 f; unsigned long long u; };
struct F4v { F2U lo, hi; };
__device__ __forceinline__ void ffma2(F2U& acc, F2U a, F2U b) {
    asm("fma.rn.f32x2 %0, %1, %2, %0;" : "+l"(acc.u) : "l"(a.u), "l"(b.u));
}
__device__ __forceinline__ float sgm(float x) { return 1.f / (1.f + __expf(-x)); }
__device__ __forceinline__ float tanh_fast(float x) {
    return 1.f - 2.f / (1.f + __expf(2.f * x));
}

// ------------------ profiling-alignment no-op launch -----------------------
__global__ void k_nop() {}

// --------------------------- init + length sort ----------------------------
__global__ void k_init(const int* __restrict__ llen) {
    int i = blockIdx.x * blockDim.x + threadIdx.x;
    if (i < BB * HH) g_hbuf[0][i] = 0.f;
    if (blockIdx.x == 0) {
        if (threadIdx.x == 0) g_sync = 0u;
        if (threadIdx.x < BB) {
            int b  = threadIdx.x;
            int Lb = llen[b];
            int r = 0, mx = 0;
            #pragma unroll 4
            for (int j = 0; j < BB; j++) {
                int Lj = llen[j];
                r  += (Lj < Lb) || (Lj == Lb && j < b);
                mx  = max(mx, Lj);
            }
            g_slot2b[r] = b;
            g_Lslot[r]  = Lb;
            if (threadIdx.x == 0) g_maxL = mx;
        }
    }
}

// ---------------- K1: pre = gather(embed) @ i2h_w^T + i2h_b ----------------
// Re-tiled for early exit: tile = ONE batch row b x 128 consecutive t.
// m = b*512 + t; blockIdx.y encodes (b = by>>2, tc = by&3). A whole tile is
// dead (never consumed by the LSTM) when tc*128 > label_len[b] -> return.
// BK=16 double-buffered, 8x8 per-thread FFMA2 (69% fma pipe measured).
__global__ __launch_bounds__(256, 2)
void k_pre(const int* __restrict__ label, const float* __restrict__ embed_w,
           const float* __restrict__ i2h_w, const float* __restrict__ i2h_b,
           const int* __restrict__ llen)
{
    const int by = blockIdx.y;
    const int b_ = by >> 2, tc = by & 3;
    if (tc * 128 > llen[b_]) return;       // dead tile: pre[t][b] never read

    __shared__ __align__(16) float As[2][16][128];
    __shared__ __align__(16) float Ws[2][16][128];

    const int tid = threadIdx.x;
    const int tx = tid & 15, ty = tid >> 4;
    const int n0 = blockIdx.x * 128;
    const int ml = tid >> 1, lk = (tid & 1) * 8;

    const int t_ = tc * 128 + ml;
    const float* arow = embed_w + (size_t)label[b_ * TT + t_] * EE;
    const float* wrow = i2h_w + (size_t)(n0 + ml) * EE;

    F2U acc[8][4];
    #pragma unroll
    for (int i = 0; i < 8; i++)
        #pragma unroll
        for (int j = 0; j < 4; j++) acc[i][j].u = 0ull;

    float4 ra0 = *(const float4*)(arow + lk);
    float4 ra1 = *(const float4*)(arow + lk + 4);
    float4 rw0 = *(const float4*)(wrow + lk);
    float4 rw1 = *(const float4*)(wrow + lk + 4);

    #pragma unroll 1
    for (int ko = 0; ko < EE / 16; ++ko) {
        const int buf = ko & 1;
        As[buf][lk + 0][ml] = ra0.x; As[buf][lk + 1][ml] = ra0.y;
        As[buf][lk + 2][ml] = ra0.z; As[buf][lk + 3][ml] = ra0.w;
        As[buf][lk + 4][ml] = ra1.x; As[buf][lk + 5][ml] = ra1.y;
        As[buf][lk + 6][ml] = ra1.z; As[buf][lk + 7][ml] = ra1.w;
        Ws[buf][lk + 0][ml] = rw0.x; Ws[buf][lk + 1][ml] = rw0.y;
        Ws[buf][lk + 2][ml] = rw0.z; Ws[buf][lk + 3][ml] = rw0.w;
        Ws[buf][lk + 4][ml] = rw1.x; Ws[buf][lk + 5][ml] = rw1.y;
        Ws[buf][lk + 6][ml] = rw1.z; Ws[buf][lk + 7][ml] = rw1.w;
        __syncthreads();
        if (ko + 1 < EE / 16) {
            const int kb = (ko + 1) * 16 + lk;
            ra0 = *(const float4*)(arow + kb);
            ra1 = *(const float4*)(arow + kb + 4);
            rw0 = *(const float4*)(wrow + kb);
            rw1 = *(const float4*)(wrow + kb + 4);
        }
        #pragma unroll
        for (int k = 0; k < 16; ++k) {
            float4 aA = *(const float4*)&As[buf][k][ty * 8];       // broadcast
            float4 aB = *(const float4*)&As[buf][k][ty * 8 + 4];   // broadcast
            F4v bA = *(const F4v*)&Ws[buf][k][tx * 4];             // conflict-free
            F4v bB = *(const F4v*)&Ws[buf][k][64 + tx * 4];        // conflict-free
            float av[8] = {aA.x, aA.y, aA.z, aA.w, aB.x, aB.y, aB.z, aB.w};
            #pragma unroll
            for (int i = 0; i < 8; i++) {
                F2U ad; ad.f.x = av[i]; ad.f.y = av[i];
                ffma2(acc[i][0], ad, bA.lo);
                ffma2(acc[i][1], ad, bA.hi);
                ffma2(acc[i][2], ad, bB.lo);
                ffma2(acc[i][3], ad, bB.hi);
            }
        }
    }

    const float4 bi0 = *(const float4*)(i2h_b + n0 + tx * 4);
    const float4 bi1 = *(const float4*)(i2h_b + n0 + 64 + tx * 4);
    #pragma unroll
    for (int i = 0; i < 8; i++) {
        const int trow = tc * 128 + ty * 8 + i;
        float* op = g_pre + ((size_t)trow * BB + b_) * G5 + n0 + tx * 4;
        float4 o0, o1;
        o0.x = acc[i][0].f.x + bi0.x; o0.y = acc[i][0].f.y + bi0.y;
        o0.z = acc[i][1].f.x + bi0.z; o0.w = acc[i][1].f.y + bi0.w;
        o1.x = acc[i][2].f.x + bi1.x; o1.y = acc[i][2].f.y + bi1.y;
        o1.z = acc[i][3].f.x + bi1.z; o1.w = acc[i][3].f.y + bi1.w;
        *(float4*)op        = o0;
        *(float4*)(op + 64) = o1;
    }
}

// ------------------------- K2: persistent LSTM -----------------------------
// R12 compute layout (measured best) + coalesced h-write staging:
// gate outputs go through sm_h[64][9] (conflict-free), then 128 threads
// store float4 runs -> full 32B sectors instead of 8x-amplified scalars.
__global__ __launch_bounds__(256, 1)
void k_lstm(const float* __restrict__ h2h_w, const float* __restrict__ h2h_b)
{
    extern __shared__ float sm[];
    float* w_s  = sm;                          // [40][512]      = 20480 f
    float* h_s  = sm + 40 * HH;                // [2][32][64][4] = 16384 f
    float* sm_h = sm + 40 * HH + 16384;        // [64][9]        =   576 f

    const int tid = threadIdx.x;
    const int u   = tid >> 5;
    const int bp  = tid & 31;
    const int blk = blockIdx.x;
    const int ug  = blk >> 1;
    const int sg  = blk & 1;
    const int ju  = ug * UB + u;
    const int s0l = bp, s1l = bp + 32;
    const int s0  = sg * SBL + s0l;
    const int s1  = sg * SBL + s1l;

    for (int i = tid; i < 40 * HH / 4; i += 256) {
        int r = i / (HH / 4), k4 = i % (HH / 4);
        int g = r >> 3, uu = r & 7;
        *(float4*)(w_s + r * HH + k4 * 4) =
            *(const float4*)(h2h_w + (size_t)(g * HH + ug * UB + uu) * HH + k4 * 4);
    }

    float bias[5];
    #pragma unroll
    for (int g = 0; g < 5; g++) bias[g] = h2h_b[g * HH + ju];

    const int bA = g_slot2b[s0], bB = g_slot2b[s1];
    const int LA = g_Lslot[s0],  LB = g_Lslot[s1];
    const int maxT = g_maxL;

    const int ls = tid >> 2, lh = tid & 3;
    const int Lrow = g_Lslot[sg * SBL + ls];

    // coalesced h-writer mapping (tid < 128): row rw_, unit-half hf
    const int rw_ = tid >> 1, hf = tid & 1;
    const int Lw  = g_Lslot[sg * SBL + (rw_ & 63)];

    float cA = 0.f, cB = 0.f;
    __syncthreads();

    #pragma unroll 1
    for (int t = 0; t <= maxT; ++t) {
        const float* hcur = g_hbuf[t % 3];
        float*       hnxt = g_hbuf[(t + 1) % 3];
        const bool actA = (t <= LA), actB = (t <= LB);
        const bool stg  = (t <= Lrow);
        const bool anyA = __any_sync(0xffffffffu, actA);
        const bool anyB = __any_sync(0xffffffffu, actB);

        F2U accA[5], accB[5];
        #pragma unroll
        for (int g = 0; g < 5; g++) { accA[g].u = 0ull; accB[g].u = 0ull; }

        float pvA[5], pvB[5];
        #pragma unroll
        for (int g = 0; g < 5; g++) { pvA[g] = 0.f; pvB[g] = 0.f; }
        if (actA) {
            #pragma unroll
            for (int g = 0; g < 5; g++)
                pvA[g] = __ldg(&g_pre[((size_t)t * BB + bA) * G5 + g * HH + ju]);
        }
        if (actB) {
            #pragma unroll
            for (int g = 0; g < 5; g++)
                pvB[g] = __ldg(&g_pre[((size_t)t * BB + bB) * G5 + g * HH + ju]);
        }

        float4 rg[8];
        if (stg) {
            const float* src = hcur + (sg * SBL + ls) * HH + lh * 32;
            #pragma unroll
            for (int q = 0; q < 8; q++) rg[q] = __ldcg((const float4*)(src + q * 4));
        }

        #pragma unroll 1
        for (int ch = 0; ch < HH / CKL; ++ch) {
            float* hb = h_s + (ch & 1) * (32 * SBL * 4);
            if (stg) {
                #pragma unroll
                for (int q = 0; q < 8; q++)
                    *(float4*)(hb + ((lh * 8 + q) * SBL + ls) * 4) = rg[q];
            }
            __syncthreads();
            if (stg && ch + 1 < HH / CKL) {
                const float* src = hcur + (sg * SBL + ls) * HH
                                   + (ch + 1) * CKL + lh * 32;
                #pragma unroll
                for (int q = 0; q < 8; q++) rg[q] = __ldcg((const float4*)(src + q * 4));
            }
            if (anyB) {
                const F4v* hp = (const F4v*)hb;
                const float* wbase = w_s + ch * CKL;
                if (anyA) {
                    #pragma unroll 4
                    for (int kq = 0; kq < CKL / 4; ++kq) {
                        F4v hA_ = hp[kq * SBL + s0l];
                        F4v hB_ = hp[kq * SBL + s1l];
                        #pragma unroll
                        for (int g = 0; g < 5; g++) {
                            F4v wv = *(const F4v*)(wbase
                                     + (size_t)(g * UB + u) * HH + kq * 4);
                            ffma2(accA[g], hA_.lo, wv.lo);
                            ffma2(accA[g], hA_.hi, wv.hi);
                            ffma2(accB[g], hB_.lo, wv.lo);
                            ffma2(accB[g], hB_.hi, wv.hi);
                        }
                    }
                } else {
                    #pragma unroll 4
                    for (int kq = 0; kq < CKL / 4; ++kq) {
                        F4v hB_ = hp[kq * SBL + s1l];
                        #pragma unroll
                        for (int g = 0; g < 5; g++) {
                            F4v wv = *(const F4v*)(wbase
                                     + (size_t)(g * UB + u) * HH + kq * 4);
                            ffma2(accB[g], hB_.lo, wv.lo);
                            ffma2(accB[g], hB_.hi, wv.hi);
                        }
                    }
                }
            }
        }

        if (actB) {
            float s[5];
            #pragma unroll
            for (int g = 0; g < 5; g++)
                s[g] = accB[g].f.x + accB[g].f.y + bias[g] + pvB[g];
            float ig = sgm(s[0]), fg = sgm(s[1]), og = sgm(s[2]);
            float av = fmaxf(s[3], s[4]);
            cB = fg * cB + ig * av;
            float nh = og * tanh_fast(cB);
            sm_h[s1l * 9 + u] = nh;                       // conflict-free (9⊥32)
            if (t == LB) g_xsel[bB * HH + ju] = nh;
        }
        if (actA) {
            float s[5];
            #pragma unroll
            for (int g = 0; g < 5; g++)
                s[g] = accA[g].f.x + accA[g].f.y + bias[g] + pvA[g];
            float ig = sgm(s[0]), fg = sgm(s[1]), og = sgm(s[2]);
            float av = fmaxf(s[3], s[4]);
            cA = fg * cA + ig * av;
            float nh = og * tanh_fast(cA);
            sm_h[s0l * 9 + u] = nh;
            if (t == LA) g_xsel[bA * HH + ju] = nh;
        }
        __syncthreads();
        if (tid < 128 && t <= Lw) {           // coalesced h write: full sectors
            float4 o;
            o.x = sm_h[rw_ * 9 + hf * 4 + 0];
            o.y = sm_h[rw_ * 9 + hf * 4 + 1];
            o.z = sm_h[rw_ * 9 + hf * 4 + 2];
            o.w = sm_h[rw_ * 9 + hf * 4 + 3];
            *(float4*)(hnxt + (size_t)(sg * SBL + rw_) * HH + ug * UB + hf * 4) = o;
        }

        __syncthreads();
        if (tid == 0) {
            asm volatile("red.release.gpu.global.add.u32 [%0], 1;"
                         :: "l"(&g_sync) : "memory");
            const unsigned tgt = (unsigned)(t + 1) * NBLK;
            unsigned v;
            do {
                asm volatile("ld.acquire.gpu.u32 %0, [%1];"
                             : "=r"(v) : "l"(&g_sync));
            } while (v < tgt);
        }
        __syncthreads();
    }
}

// ---------------- K3: linear + batchnorm (+relu), one block per column -----
__global__ __launch_bounds__(128, 8)
void k_head(const float* __restrict__ w, const float* __restrict__ bias,
            const float* __restrict__ gam, const float* __restrict__ bet,
            float* __restrict__ dout, int phase)
{
    __shared__ float w_s[LEE];
    __shared__ float red[BB];
    const int n = blockIdx.x, b = threadIdx.x;
    const float* x   = phase ? g_z0 : g_xsel;
    float*       out = phase ? dout : g_z0;

    for (int k = b; k < LEE; k += BB) w_s[k] = w[(size_t)n * LEE + k];
    __syncthreads();

    float s = 0.f;
    const float* xr = x + (size_t)b * LEE;
    #pragma unroll 4
    for (int k = 0; k < LEE; k += 4) {
        float4 xv = *(const float4*)(xr + k);
        float4 wv = *(const float4*)(w_s + k);
        s += xv.x * wv.x + xv.y * wv.y + xv.z * wv.z + xv.w * wv.w;
    }
    s += bias[n];

    red[b] = s; __syncthreads();
    #pragma unroll
    for (int off = 64; off > 0; off >>= 1) {
        if (b < off) red[b] += red[b + off];
        __syncthreads();
    }
    const float mean = red[0] * (1.f / BB);
    __syncthreads();
    const float d = s - mean;
    red[b] = d * d; __syncthreads();
    #pragma unroll
    for (int off = 64; off > 0; off >>= 1) {
        if (b < off) red[b] += red[b + off];
        __syncthreads();
    }
    const float var = red[0] * (1.f / BB);

    float y = d * rsqrtf(var + EPSV) * gam[n] + bet[n];
    if (!phase) y = fmaxf(y, 0.f);
    out[(size_t)b * LEE + n] = y;
}

// ------------------------------ launcher -----------------------------------
extern "C" void kernel_launch(void* const* d_in, const int* in_sizes, int n_in,
                              void* d_out, int out_size)
{
    const int*   label    = (const int*)  d_in[0];
    const int*   llen     = (const int*)  d_in[1];
    const float* embed_w  = (const float*)d_in[2];
    const float* i2h_w    = (const float*)d_in[3];
    const float* i2h_b    = (const float*)d_in[4];
    const float* h2h_w    = (const float*)d_in[5];
    const float* h2h_b    = (const float*)d_in[6];
    const float* lin0_w   = (const float*)d_in[7];
    const float* lin0_b   = (const float*)d_in[8];
    const float* bn0_g    = (const float*)d_in[9];
    const float* bn0_b    = (const float*)d_in[10];
    const float* lin1_w   = (const float*)d_in[11];
    const float* lin1_b   = (const float*)d_in[12];
    const float* bn1_g    = (const float*)d_in[13];
    const float* bn1_b    = (const float*)d_in[14];
    float*       out      = (float*)d_out;

    const int smem_lstm = (40 * HH + 2 * 32 * SBL * 4 + 576) * (int)sizeof(float);
    static int attr_done = 0;
    if (!attr_done) {
        cudaFuncSetAttribute(k_lstm, cudaFuncAttributeMaxDynamicSharedMemorySize,
                             smem_lstm);
        attr_done = 1;
    }

    k_init<<<256, 256>>>(llen);
    k_pre<<<dim3(G5 / 128, BB * 4), 256>>>(label, embed_w, i2h_w, i2h_b, llen);
    k_nop<<<1, 32>>>();
    k_lstm<<<NBLK, 256, smem_lstm>>>(h2h_w, h2h_b);
    k_head<<<LEE, BB>>>(lin0_w, lin0_b, bn0_g, bn0_b, out, 0);
    k_head<<<LEE, BB>>>(lin1_w, lin1_b, bn1_g, bn1_b, out, 1);
}